// round 10
// baseline (speedup 1.0000x reference)
#include <cuda_runtime.h>
#include <math.h>

#define BB 32
#define NN 16384
#define KK 64
#define CHUNKS 16
#define ROWS_PER_CHUNK (NN / CHUNKS)   // 1024
#define BLOCKS_PER_BATCH (CHUNKS * 2)  // 32

// Deterministic scratch: [tensor][b][chunk][k][4]  (sg, sx, sy, sz)
__device__ float g_partials[2 * BB * CHUNKS * KK * 4];
// Per-batch arrival counters (reset by finalizer -> graph-replay safe)
__device__ int g_count[BB];

__device__ __forceinline__ void warp_reduce_n(float* v, int n)
{
    for (int o = 16; o; o >>= 1)
        for (int j = 0; j < n; ++j)
            v[j] += __shfl_xor_sync(0xffffffffu, v[j], o);
}

// ---------------------------------------------------------------------------
// Finalize: chunk reduction + weighted Procrustes + 3x3 SVD (R7-proven math).
// __noinline__ is load-bearing: keeps this cold path's register pressure out
// of the hot streaming loop (R4 regression: inlined tail spilled the loop).
// Called by ALL 256 threads of exactly one block per batch.
// ---------------------------------------------------------------------------
static __device__ __noinline__ void finalize_batch(int b, float* __restrict__ out)
{
    const int tid  = threadIdx.x;
    const int k    = tid;           // only k<64 carries reduction data
    const int wid  = tid >> 5;
    const int lane = tid & 31;

    __shared__ float wsum[2][16];

    float v[16];
    #pragma unroll
    for (int j = 0; j < 16; ++j) v[j] = 0.f;

    if (k < KK) {
        float sgx = 0.f, sxx = 0.f, syx = 0.f, szx = 0.f;
        float sgy = 0.f, sxy = 0.f, syy = 0.f, szy = 0.f;
        #pragma unroll
        for (int c = 0; c < CHUNKS; ++c) {
            const float4 px = __ldcg(reinterpret_cast<const float4*>(
                &g_partials[(((size_t)0 * BB + b) * CHUNKS + c) * (KK * 4) + k * 4]));
            sgx += px.x; sxx += px.y; syx += px.z; szx += px.w;
            const float4 py = __ldcg(reinterpret_cast<const float4*>(
                &g_partials[(((size_t)1 * BB + b) * CHUNKS + c) * (KK * 4) + k * 4]));
            sgy += py.x; sxy += py.y; syy += py.z; szy += py.w;
        }
        const float EPSf = 1e-8f;
        const float pix = sgx * (1.0f / (float)NN);
        const float piy = sgy * (1.0f / (float)NN);
        const float rpx = __fdividef(1.0f, pix + EPSf);
        const float rpy = __fdividef(1.0f, piy + EPSf);
        const float mux0 = sxx * rpx, mux1 = syx * rpx, mux2 = szx * rpx;
        const float muy0 = sxy * rpy, muy1 = syy * rpy, muy2 = szy * rpy;
        const float w = pix * piy;

        v[0] = w;
        v[1] = w * mux0;  v[2] = w * mux1;  v[3] = w * mux2;
        v[4] = w * muy0;  v[5] = w * muy1;  v[6] = w * muy2;
        v[7]  = w * mux0 * muy0; v[8]  = w * mux0 * muy1; v[9]  = w * mux0 * muy2;
        v[10] = w * mux1 * muy0; v[11] = w * mux1 * muy1; v[12] = w * mux1 * muy2;
        v[13] = w * mux2 * muy0; v[14] = w * mux2 * muy1; v[15] = w * mux2 * muy2;
    }
    if (wid < 2) {
        warp_reduce_n(v, 16);
        if (lane == 0)
            #pragma unroll
            for (int j = 0; j < 16; ++j) wsum[wid][j] = v[j];
    }
    __syncthreads();

    if (tid == 0) {
        const float EPSf = 1e-8f;
        float s[16];
        #pragma unroll
        for (int j = 0; j < 16; ++j) s[j] = wsum[0][j] + wsum[1][j];

        const float wtot = s[0];
        const float ws = __fdividef(1.0f, wtot + EPSf);
        const float cs[3] = { s[1] * ws, s[2] * ws, s[3] * ws };   // c_s
        const float ct[3] = { s[4] * ws, s[5] * ws, s[6] * ws };   // c_t

        // H = S_xy - wtot * c_s c_t^T
        float H[3][3];
        #pragma unroll
        for (int i = 0; i < 3; ++i)
            #pragma unroll
            for (int j = 0; j < 3; ++j)
                H[i][j] = s[7 + i * 3 + j] - wtot * cs[i] * ct[j];

        // Scale H to O(1) for healthy fp32 conditioning in HtH.
        float hmax = 0.f;
        for (int i = 0; i < 3; ++i)
            for (int j = 0; j < 3; ++j) hmax = fmaxf(hmax, fabsf(H[i][j]));
        const float hscale = (hmax > 1e-30f) ? __fdividef(1.0f, hmax) : 1.0f;
        float Hs[3][3];
        for (int i = 0; i < 3; ++i)
            for (int j = 0; j < 3; ++j) Hs[i][j] = H[i][j] * hscale;

        // A = Hs^T Hs (symmetric)
        float A[3][3];
        for (int i = 0; i < 3; ++i)
            for (int j = 0; j < 3; ++j)
                A[i][j] = Hs[0][i] * Hs[0][j] + Hs[1][i] * Hs[1][j] + Hs[2][i] * Hs[2][j];

        float V[3][3] = {{1, 0, 0}, {0, 1, 0}, {0, 0, 1}};
        // Cyclic Jacobi, 5 sweeps. IEEE sqrtf (inf-safe; fast_sqrt NaN'd in R6).
        #pragma unroll 1
        for (int sweep = 0; sweep < 5; ++sweep) {
            const int PQ[3][2] = {{0, 1}, {0, 2}, {1, 2}};
            #pragma unroll
            for (int m = 0; m < 3; ++m) {
                const int p = PQ[m][0], q = PQ[m][1];
                const float apq = A[p][q];
                if (fabsf(apq) < 1e-35f) continue;
                const float tau = __fdividef(A[q][q] - A[p][p], 2.0f * apq);
                float tt = __fdividef(copysignf(1.0f, tau),
                                      fabsf(tau) + sqrtf(1.0f + tau * tau));
                if (!isfinite(tt)) tt = 0.0f;
                const float c = rsqrtf(1.0f + tt * tt);
                const float s2 = tt * c;
                const float app = A[p][p], aqq = A[q][q];
                A[p][p] = app - tt * apq;
                A[q][q] = aqq + tt * apq;
                A[p][q] = A[q][p] = 0.0f;
                const int r = 3 - p - q;
                const float arp = A[r][p], arq = A[r][q];
                A[r][p] = A[p][r] = c * arp - s2 * arq;
                A[r][q] = A[q][r] = s2 * arp + c * arq;
                #pragma unroll
                for (int i = 0; i < 3; ++i) {
                    const float vip = V[i][p], viq = V[i][q];
                    V[i][p] = c * vip - s2 * viq;
                    V[i][q] = s2 * vip + c * viq;
                }
            }
        }

        float eig[3] = {A[0][0], A[1][1], A[2][2]};
        // Sort descending, permuting V columns
        #pragma unroll
        for (int i = 0; i < 2; ++i)
            #pragma unroll
            for (int j = i + 1; j < 3; ++j)
                if (eig[j] > eig[i]) {
                    float tmp = eig[i]; eig[i] = eig[j]; eig[j] = tmp;
                    for (int r = 0; r < 3; ++r) {
                        tmp = V[r][i]; V[r][i] = V[r][j]; V[r][j] = tmp;
                    }
                }

        // U columns: u0 = normalize(Hs v0); u1 = GS(Hs v1); u2 = u0 x u1
        float U[3][3];
        {
            float u0[3], u1[3];
            for (int i = 0; i < 3; ++i)
                u0[i] = Hs[i][0] * V[0][0] + Hs[i][1] * V[1][0] + Hs[i][2] * V[2][0];
            const float nn0 = u0[0] * u0[0] + u0[1] * u0[1] + u0[2] * u0[2];
            if (nn0 > 1e-40f) { const float r = rsqrtf(nn0); u0[0] *= r; u0[1] *= r; u0[2] *= r; }
            else { u0[0] = 1; u0[1] = 0; u0[2] = 0; }

            for (int i = 0; i < 3; ++i)
                u1[i] = Hs[i][0] * V[0][1] + Hs[i][1] * V[1][1] + Hs[i][2] * V[2][1];
            const float d01 = u1[0] * u0[0] + u1[1] * u0[1] + u1[2] * u0[2];
            u1[0] -= d01 * u0[0]; u1[1] -= d01 * u0[1]; u1[2] -= d01 * u0[2];
            const float nn1 = u1[0] * u1[0] + u1[1] * u1[1] + u1[2] * u1[2];
            if (nn1 > 1e-40f) { const float r = rsqrtf(nn1); u1[0] *= r; u1[1] *= r; u1[2] *= r; }
            else {
                const float ax = fabsf(u0[0]), ay = fabsf(u0[1]), az = fabsf(u0[2]);
                float e[3] = {0, 0, 0};
                if (ax <= ay && ax <= az) e[0] = 1;
                else if (ay <= az) e[1] = 1;
                else e[2] = 1;
                u1[0] = u0[1] * e[2] - u0[2] * e[1];
                u1[1] = u0[2] * e[0] - u0[0] * e[2];
                u1[2] = u0[0] * e[1] - u0[1] * e[0];
                const float rn = rsqrtf(u1[0] * u1[0] + u1[1] * u1[1] + u1[2] * u1[2]);
                u1[0] *= rn; u1[1] *= rn; u1[2] *= rn;
            }
            const float u2[3] = { u0[1] * u1[2] - u0[2] * u1[1],
                                  u0[2] * u1[0] - u0[0] * u1[2],
                                  u0[0] * u1[1] - u0[1] * u1[0] };
            for (int i = 0; i < 3; ++i) {
                U[i][0] = u0[i]; U[i][1] = u1[i]; U[i][2] = u2[i];
            }
        }

        const float detV =
            V[0][0] * (V[1][1] * V[2][2] - V[1][2] * V[2][1]) -
            V[0][1] * (V[1][0] * V[2][2] - V[1][2] * V[2][0]) +
            V[0][2] * (V[1][0] * V[2][1] - V[1][1] * V[2][0]);
        const float detU =
            U[0][0] * (U[1][1] * U[2][2] - U[1][2] * U[2][1]) -
            U[0][1] * (U[1][0] * U[2][2] - U[1][2] * U[2][0]) +
            U[0][2] * (U[1][0] * U[2][1] - U[1][1] * U[2][0]);
        const float d = detV * detU;   // det(V U^T)

        // R = V diag(1,1,d) U^T
        float R[3][3];
        for (int i = 0; i < 3; ++i)
            for (int j = 0; j < 3; ++j)
                R[i][j] = V[i][0] * U[j][0] + V[i][1] * U[j][1] + d * V[i][2] * U[j][2];

        // t = c_t - R c_s
        float tv[3];
        for (int i = 0; i < 3; ++i)
            tv[i] = ct[i] - (R[i][0] * cs[0] + R[i][1] * cs[1] + R[i][2] * cs[2]);

        // Output: R (B*9) then t (B*3)
        for (int i = 0; i < 3; ++i)
            for (int j = 0; j < 3; ++j)
                out[b * 9 + i * 3 + j] = R[i][j];
        for (int i = 0; i < 3; ++i)
            out[BB * 9 + b * 3 + i] = tv[i];

        // Reset counter for next graph replay (all arrivals already counted)
        g_count[b] = 0;
    }
}

// ---------------------------------------------------------------------------
// Fused kernel: R3-proven streaming loop (launch_bounds(256,8), unroll 4,
// __ldcs) + atomic-counter last-block finalize via __noinline__ cold call.
// ---------------------------------------------------------------------------
__global__ void __launch_bounds__(256, 8) fused_kernel(
    const float* __restrict__ pts_x, const float* __restrict__ pts_y,
    const float* __restrict__ gam_x, const float* __restrict__ gam_y,
    float* __restrict__ out)
{
    const int chunk = blockIdx.x;
    const int b     = blockIdx.y;
    const int tsel  = blockIdx.z;
    const float* __restrict__ pts = tsel ? pts_y : pts_x;
    const float* __restrict__ gam = tsel ? gam_y : gam_x;

    const int tid = threadIdx.x;
    const int kg  = tid & 15;   // k4 group
    const int rg  = tid >> 4;   // row group 0..15

    float sg[4] = {0.f, 0.f, 0.f, 0.f};
    float sx[4] = {0.f, 0.f, 0.f, 0.f};
    float sy[4] = {0.f, 0.f, 0.f, 0.f};
    float sz[4] = {0.f, 0.f, 0.f, 0.f};

    const int n0 = chunk * ROWS_PER_CHUNK;

    #pragma unroll 4
    for (int r = rg; r < ROWS_PER_CHUNK; r += 16) {
        const size_t n = (size_t)b * NN + (size_t)(n0 + r);
        // gamma is streamed once: evict-first so it never thrashes L2
        const float4 g = __ldcs(reinterpret_cast<const float4*>(gam + n * KK + 4 * kg));
        const float px = __ldg(pts + n * 3 + 0);
        const float py = __ldg(pts + n * 3 + 1);
        const float pz = __ldg(pts + n * 3 + 2);
        sg[0] += g.x; sg[1] += g.y; sg[2] += g.z; sg[3] += g.w;
        sx[0] = fmaf(g.x, px, sx[0]); sx[1] = fmaf(g.y, px, sx[1]);
        sx[2] = fmaf(g.z, px, sx[2]); sx[3] = fmaf(g.w, px, sx[3]);
        sy[0] = fmaf(g.x, py, sy[0]); sy[1] = fmaf(g.y, py, sy[1]);
        sy[2] = fmaf(g.z, py, sy[2]); sy[3] = fmaf(g.w, py, sy[3]);
        sz[0] = fmaf(g.x, pz, sz[0]); sz[1] = fmaf(g.y, pz, sz[1]);
        sz[2] = fmaf(g.z, pz, sz[2]); sz[3] = fmaf(g.w, pz, sz[3]);
    }

    // Block reduction across the 16 row-groups: smem[rg][k][val]
    __shared__ float smem[16 * KK * 4];
    #pragma unroll
    for (int j = 0; j < 4; ++j) {
        const int k = 4 * kg + j;
        float* p = &smem[(rg * KK + k) * 4];
        p[0] = sg[j]; p[1] = sx[j]; p[2] = sy[j]; p[3] = sz[j];
    }
    __syncthreads();

    // 256 threads == 64 k * 4 vals; tid = k*4 + val
    {
        const int k   = tid >> 2;
        const int val = tid & 3;
        float acc = 0.f;
        #pragma unroll
        for (int r = 0; r < 16; ++r) acc += smem[(r * KK + k) * 4 + val];
        g_partials[(((size_t)tsel * BB + b) * CHUNKS + chunk) * (KK * 4) + tid] = acc;
    }

    // ---- arrival: last block of this batch finalizes ----
    __shared__ int isLast;
    __threadfence();                       // make partials visible device-wide
    __syncthreads();                       // all warps' STGs issued before arrive
    if (tid == 0) {
        const int old = atomicAdd(&g_count[b], 1);
        isLast = (old == BLOCKS_PER_BATCH - 1);
    }
    __syncthreads();
    if (isLast)
        finalize_batch(b, out);
}

extern "C" void kernel_launch(void* const* d_in, const int* in_sizes, int n_in,
                              void* d_out, int out_size)
{
    const float* pts_x = (const float*)d_in[0];
    const float* pts_y = (const float*)d_in[1];
    const float* gam_x = (const float*)d_in[2];
    const float* gam_y = (const float*)d_in[3];

    dim3 grid(CHUNKS, BB, 2);
    fused_kernel<<<grid, 256>>>(pts_x, pts_y, gam_x, gam_y, (float*)d_out);
}

// round 12
// speedup vs baseline: 1.8172x; 1.8172x over previous
#include <cuda_runtime.h>
#include <math.h>

#define BB 32
#define NN 16384
#define KK 64
#define CHUNKS 16
#define ROWS_PER_CHUNK (NN / CHUNKS)   // 1024
#define BLOCKS_PER_BATCH (CHUNKS * 2)  // 32

// Deterministic scratch: [tensor][b][chunk][k][4]  (sg, sx, sy, sz)
__device__ float g_partials[2 * BB * CHUNKS * KK * 4];
// Per-batch arrival counters (integer, reset by stage2 -> graph-replay safe)
__device__ int g_count[BB];

// ---------------------------------------------------------------------------
// Stage 1: per-chunk weighted reductions (pure HBM streaming).
// R3-proven config: launch_bounds(256,8), unroll 4, __ldcs. DO NOT TOUCH LOOP.
// Adds: per-batch arrival counter + PDL trigger (both after the partial store).
// ---------------------------------------------------------------------------
__global__ void __launch_bounds__(256, 8) stage1_kernel(
    const float* __restrict__ pts_x, const float* __restrict__ pts_y,
    const float* __restrict__ gam_x, const float* __restrict__ gam_y)
{
    const int chunk = blockIdx.x;
    const int b     = blockIdx.y;
    const int tsel  = blockIdx.z;
    const float* __restrict__ pts = tsel ? pts_y : pts_x;
    const float* __restrict__ gam = tsel ? gam_y : gam_x;

    const int tid = threadIdx.x;
    const int kg  = tid & 15;   // k4 group
    const int rg  = tid >> 4;   // row group 0..15

    float sg[4] = {0.f, 0.f, 0.f, 0.f};
    float sx[4] = {0.f, 0.f, 0.f, 0.f};
    float sy[4] = {0.f, 0.f, 0.f, 0.f};
    float sz[4] = {0.f, 0.f, 0.f, 0.f};

    const int n0 = chunk * ROWS_PER_CHUNK;

    #pragma unroll 4
    for (int r = rg; r < ROWS_PER_CHUNK; r += 16) {
        const size_t n = (size_t)b * NN + (size_t)(n0 + r);
        // gamma is streamed once: evict-first so it never thrashes L2
        const float4 g = __ldcs(reinterpret_cast<const float4*>(gam + n * KK + 4 * kg));
        const float px = __ldg(pts + n * 3 + 0);
        const float py = __ldg(pts + n * 3 + 1);
        const float pz = __ldg(pts + n * 3 + 2);
        sg[0] += g.x; sg[1] += g.y; sg[2] += g.z; sg[3] += g.w;
        sx[0] = fmaf(g.x, px, sx[0]); sx[1] = fmaf(g.y, px, sx[1]);
        sx[2] = fmaf(g.z, px, sx[2]); sx[3] = fmaf(g.w, px, sx[3]);
        sy[0] = fmaf(g.x, py, sy[0]); sy[1] = fmaf(g.y, py, sy[1]);
        sy[2] = fmaf(g.z, py, sy[2]); sy[3] = fmaf(g.w, py, sy[3]);
        sz[0] = fmaf(g.x, pz, sz[0]); sz[1] = fmaf(g.y, pz, sz[1]);
        sz[2] = fmaf(g.z, pz, sz[2]); sz[3] = fmaf(g.w, pz, sz[3]);
    }

    // Block reduction across the 16 row-groups: smem[rg][k][val]
    __shared__ float smem[16 * KK * 4];
    #pragma unroll
    for (int j = 0; j < 4; ++j) {
        const int k = 4 * kg + j;
        float* p = &smem[(rg * KK + k) * 4];
        p[0] = sg[j]; p[1] = sx[j]; p[2] = sy[j]; p[3] = sz[j];
    }
    __syncthreads();

    // 256 threads == 64 k * 4 vals; tid = k*4 + val
    {
        const int k   = tid >> 2;
        const int val = tid & 3;
        float acc = 0.f;
        #pragma unroll
        for (int r = 0; r < 16; ++r) acc += smem[(r * KK + k) * 4 + val];
        g_partials[(((size_t)tsel * BB + b) * CHUNKS + chunk) * (KK * 4) + tid] = acc;
    }

    // Publish: fence partials, bump this batch's counter, fire PDL trigger.
    __threadfence();
    __syncthreads();
    if (tid == 0) {
        atomicAdd(&g_count[b], 1);
        cudaTriggerProgrammaticLaunchCompletion();
    }
}

// ---------------------------------------------------------------------------
// Stage 2: PDL-launched; each block spin-waits on ITS batch's counter, so
// early batches finalize while stage1 stragglers still stream.
// Single-pass moment reduction + weighted Procrustes + 3x3 SVD (R7 math).
// ---------------------------------------------------------------------------
__device__ __forceinline__ void warp_reduce_n(float* v, int n)
{
    for (int o = 16; o; o >>= 1)
        for (int j = 0; j < n; ++j)
            v[j] += __shfl_xor_sync(0xffffffffu, v[j], o);
}

__global__ void __launch_bounds__(64) stage2_kernel(float* __restrict__ out)
{
    const int b    = blockIdx.x;
    const int k    = threadIdx.x;   // 0..63
    const int wid  = k >> 5;
    const int lane = k & 31;

    // Wait for this batch's 32 producer blocks (device-wide fenced arrivals).
    if (k == 0) {
        volatile int* cnt = &g_count[b];
        while (*cnt < BLOCKS_PER_BATCH) { }
    }
    __syncthreads();
    __threadfence();   // acquire: order partial reads after counter observation

    float sgx = 0.f, sxx = 0.f, syx = 0.f, szx = 0.f;
    float sgy = 0.f, sxy = 0.f, syy = 0.f, szy = 0.f;
    #pragma unroll
    for (int c = 0; c < CHUNKS; ++c) {
        const float4 px = __ldcg(reinterpret_cast<const float4*>(
            &g_partials[(((size_t)0 * BB + b) * CHUNKS + c) * (KK * 4) + k * 4]));
        sgx += px.x; sxx += px.y; syx += px.z; szx += px.w;
        const float4 py = __ldcg(reinterpret_cast<const float4*>(
            &g_partials[(((size_t)1 * BB + b) * CHUNKS + c) * (KK * 4) + k * 4]));
        sgy += py.x; sxy += py.y; syy += py.z; szy += py.w;
    }

    const float EPSf = 1e-8f;
    const float pix = sgx * (1.0f / (float)NN);
    const float piy = sgy * (1.0f / (float)NN);
    const float rpx = __fdividef(1.0f, pix + EPSf);
    const float rpy = __fdividef(1.0f, piy + EPSf);
    const float mux0 = sxx * rpx, mux1 = syx * rpx, mux2 = szx * rpx;
    const float muy0 = sxy * rpy, muy1 = syy * rpy, muy2 = szy * rpy;
    const float w = pix * piy;

    // --- Single-pass reduction: w, w*mux(3), w*muy(3), w*mux*muy^T(9) = 16 ---
    __shared__ float wsum[2][16];
    {
        float v[16] = {
            w,
            w * mux0, w * mux1, w * mux2,
            w * muy0, w * muy1, w * muy2,
            w * mux0 * muy0, w * mux0 * muy1, w * mux0 * muy2,
            w * mux1 * muy0, w * mux1 * muy1, w * mux1 * muy2,
            w * mux2 * muy0, w * mux2 * muy1, w * mux2 * muy2
        };
        warp_reduce_n(v, 16);
        if (lane == 0)
            #pragma unroll
            for (int j = 0; j < 16; ++j) wsum[wid][j] = v[j];
    }
    __syncthreads();

    if (k == 0) {
        float s[16];
        #pragma unroll
        for (int j = 0; j < 16; ++j) s[j] = wsum[0][j] + wsum[1][j];

        const float wtot = s[0];
        const float ws = __fdividef(1.0f, wtot + EPSf);
        const float cs[3] = { s[1] * ws, s[2] * ws, s[3] * ws };   // c_s
        const float ct[3] = { s[4] * ws, s[5] * ws, s[6] * ws };   // c_t

        // H = S_xy - wtot * c_s c_t^T
        float H[3][3];
        #pragma unroll
        for (int i = 0; i < 3; ++i)
            #pragma unroll
            for (int j = 0; j < 3; ++j)
                H[i][j] = s[7 + i * 3 + j] - wtot * cs[i] * ct[j];

        // Scale H to O(1) for healthy fp32 conditioning in HtH.
        float hmax = 0.f;
        for (int i = 0; i < 3; ++i)
            for (int j = 0; j < 3; ++j) hmax = fmaxf(hmax, fabsf(H[i][j]));
        const float hscale = (hmax > 1e-30f) ? __fdividef(1.0f, hmax) : 1.0f;
        float Hs[3][3];
        for (int i = 0; i < 3; ++i)
            for (int j = 0; j < 3; ++j) Hs[i][j] = H[i][j] * hscale;

        // A = Hs^T Hs (symmetric)
        float A[3][3];
        for (int i = 0; i < 3; ++i)
            for (int j = 0; j < 3; ++j)
                A[i][j] = Hs[0][i] * Hs[0][j] + Hs[1][i] * Hs[1][j] + Hs[2][i] * Hs[2][j];

        float V[3][3] = {{1, 0, 0}, {0, 1, 0}, {0, 0, 1}};
        // Cyclic Jacobi, 5 sweeps. IEEE sqrtf (inf-safe; fast_sqrt NaN'd in R6).
        #pragma unroll 1
        for (int sweep = 0; sweep < 5; ++sweep) {
            const int PQ[3][2] = {{0, 1}, {0, 2}, {1, 2}};
            #pragma unroll
            for (int m = 0; m < 3; ++m) {
                const int p = PQ[m][0], q = PQ[m][1];
                const float apq = A[p][q];
                if (fabsf(apq) < 1e-35f) continue;
                const float tau = __fdividef(A[q][q] - A[p][p], 2.0f * apq);
                float tt = __fdividef(copysignf(1.0f, tau),
                                      fabsf(tau) + sqrtf(1.0f + tau * tau));
                if (!isfinite(tt)) tt = 0.0f;
                const float c = rsqrtf(1.0f + tt * tt);
                const float s2 = tt * c;
                const float app = A[p][p], aqq = A[q][q];
                A[p][p] = app - tt * apq;
                A[q][q] = aqq + tt * apq;
                A[p][q] = A[q][p] = 0.0f;
                const int r = 3 - p - q;
                const float arp = A[r][p], arq = A[r][q];
                A[r][p] = A[p][r] = c * arp - s2 * arq;
                A[r][q] = A[q][r] = s2 * arp + c * arq;
                #pragma unroll
                for (int i = 0; i < 3; ++i) {
                    const float vip = V[i][p], viq = V[i][q];
                    V[i][p] = c * vip - s2 * viq;
                    V[i][q] = s2 * vip + c * viq;
                }
            }
        }

        float eig[3] = {A[0][0], A[1][1], A[2][2]};
        // Sort descending, permuting V columns
        #pragma unroll
        for (int i = 0; i < 2; ++i)
            #pragma unroll
            for (int j = i + 1; j < 3; ++j)
                if (eig[j] > eig[i]) {
                    float tmp = eig[i]; eig[i] = eig[j]; eig[j] = tmp;
                    for (int r = 0; r < 3; ++r) {
                        tmp = V[r][i]; V[r][i] = V[r][j]; V[r][j] = tmp;
                    }
                }

        // U columns: u0 = normalize(Hs v0); u1 = GS(Hs v1); u2 = u0 x u1
        float U[3][3];
        {
            float u0[3], u1[3];
            for (int i = 0; i < 3; ++i)
                u0[i] = Hs[i][0] * V[0][0] + Hs[i][1] * V[1][0] + Hs[i][2] * V[2][0];
            const float nn0 = u0[0] * u0[0] + u0[1] * u0[1] + u0[2] * u0[2];
            if (nn0 > 1e-40f) { const float r = rsqrtf(nn0); u0[0] *= r; u0[1] *= r; u0[2] *= r; }
            else { u0[0] = 1; u0[1] = 0; u0[2] = 0; }

            for (int i = 0; i < 3; ++i)
                u1[i] = Hs[i][0] * V[0][1] + Hs[i][1] * V[1][1] + Hs[i][2] * V[2][1];
            const float d01 = u1[0] * u0[0] + u1[1] * u0[1] + u1[2] * u0[2];
            u1[0] -= d01 * u0[0]; u1[1] -= d01 * u0[1]; u1[2] -= d01 * u0[2];
            const float nn1 = u1[0] * u1[0] + u1[1] * u1[1] + u1[2] * u1[2];
            if (nn1 > 1e-40f) { const float r = rsqrtf(nn1); u1[0] *= r; u1[1] *= r; u1[2] *= r; }
            else {
                // pick any unit vector orthogonal to u0
                const float ax = fabsf(u0[0]), ay = fabsf(u0[1]), az = fabsf(u0[2]);
                float e[3] = {0, 0, 0};
                if (ax <= ay && ax <= az) e[0] = 1;
                else if (ay <= az) e[1] = 1;
                else e[2] = 1;
                u1[0] = u0[1] * e[2] - u0[2] * e[1];
                u1[1] = u0[2] * e[0] - u0[0] * e[2];
                u1[2] = u0[0] * e[1] - u0[1] * e[0];
                const float rn = rsqrtf(u1[0] * u1[0] + u1[1] * u1[1] + u1[2] * u1[2]);
                u1[0] *= rn; u1[1] *= rn; u1[2] *= rn;
            }
            const float u2[3] = { u0[1] * u1[2] - u0[2] * u1[1],
                                  u0[2] * u1[0] - u0[0] * u1[2],
                                  u0[0] * u1[1] - u0[1] * u1[0] };
            for (int i = 0; i < 3; ++i) {
                U[i][0] = u0[i]; U[i][1] = u1[i]; U[i][2] = u2[i];
            }
        }

        const float detV =
            V[0][0] * (V[1][1] * V[2][2] - V[1][2] * V[2][1]) -
            V[0][1] * (V[1][0] * V[2][2] - V[1][2] * V[2][0]) +
            V[0][2] * (V[1][0] * V[2][1] - V[1][1] * V[2][0]);
        const float detU =
            U[0][0] * (U[1][1] * U[2][2] - U[1][2] * U[2][1]) -
            U[0][1] * (U[1][0] * U[2][2] - U[1][2] * U[2][0]) +
            U[0][2] * (U[1][0] * U[2][1] - U[1][1] * U[2][0]);
        const float d = detV * detU;   // det(V U^T)

        // R = V diag(1,1,d) U^T
        float R[3][3];
        for (int i = 0; i < 3; ++i)
            for (int j = 0; j < 3; ++j)
                R[i][j] = V[i][0] * U[j][0] + V[i][1] * U[j][1] + d * V[i][2] * U[j][2];

        // t = c_t - R c_s
        float tv[3];
        for (int i = 0; i < 3; ++i)
            tv[i] = ct[i] - (R[i][0] * cs[0] + R[i][1] * cs[1] + R[i][2] * cs[2]);

        // Output: R (B*9) then t (B*3)
        for (int i = 0; i < 3; ++i)
            for (int j = 0; j < 3; ++j)
                out[b * 9 + i * 3 + j] = R[i][j];
        for (int i = 0; i < 3; ++i)
            out[BB * 9 + b * 3 + i] = tv[i];

        // Reset counter for the next graph replay (all arrivals consumed)
        g_count[b] = 0;
    }
}

extern "C" void kernel_launch(void* const* d_in, const int* in_sizes, int n_in,
                              void* d_out, int out_size)
{
    const float* pts_x = (const float*)d_in[0];
    const float* pts_y = (const float*)d_in[1];
    const float* gam_x = (const float*)d_in[2];
    const float* gam_y = (const float*)d_in[3];

    dim3 grid1(CHUNKS, BB, 2);
    stage1_kernel<<<grid1, 256>>>(pts_x, pts_y, gam_x, gam_y);

    // PDL launch: stage2 co-schedules while stage1's tail drains; each block
    // spin-waits on its own batch counter (device-fenced arrivals).
    cudaLaunchConfig_t cfg = {};
    cfg.gridDim  = dim3(BB, 1, 1);
    cfg.blockDim = dim3(KK, 1, 1);
    cfg.stream   = 0;
    cudaLaunchAttribute attr[1];
    attr[0].id = cudaLaunchAttributeProgrammaticStreamSerialization;
    attr[0].val.programmaticStreamSerializationAllowed = 1;
    cfg.attrs    = attr;
    cfg.numAttrs = 1;
    float* outp = (float*)d_out;
    if (cudaLaunchKernelEx(&cfg, stage2_kernel, outp) != cudaSuccess) {
        // Fallback: plain launch (still correct — spin-waits pass instantly
        // because stage1 has fully completed under stream ordering).
        stage2_kernel<<<BB, KK>>>(outp);
    }
}

// round 13
// speedup vs baseline: 1.8732x; 1.0308x over previous
#include <cuda_runtime.h>
#include <math.h>

#define BB 32
#define NN 16384
#define KK 64
#define CHUNKS 16
#define ROWS_PER_CHUNK (NN / CHUNKS)   // 1024

// Deterministic scratch: [tensor][b][chunk][k][4]  (sg, sx, sy, sz)
__device__ float g_partials[2 * BB * CHUNKS * KK * 4];

// ---------------------------------------------------------------------------
// Stage 1: per-chunk weighted reductions (pure HBM streaming).
// R3-proven: launch_bounds(256,8), unroll 4, __ldcs on gamma.
// New: points staged to smem (union with reduction buffer -> 16KB total),
// so the hot loop issues ONLY the gamma LDG.128 stream.
// ---------------------------------------------------------------------------
__global__ void __launch_bounds__(256, 8) stage1_kernel(
    const float* __restrict__ pts_x, const float* __restrict__ pts_y,
    const float* __restrict__ gam_x, const float* __restrict__ gam_y)
{
    const int chunk = blockIdx.x;
    const int b     = blockIdx.y;
    const int tsel  = blockIdx.z;
    const float* __restrict__ pts = tsel ? pts_y : pts_x;
    const float* __restrict__ gam = tsel ? gam_y : gam_x;

    const int tid = threadIdx.x;
    const int kg  = tid & 15;   // k4 group
    const int rg  = tid >> 4;   // row group 0..15

    const int n0 = chunk * ROWS_PER_CHUNK;

    // Union: points staging (12KB) during the loop, reduction buffer (16KB) after.
    __shared__ union {
        float pts[ROWS_PER_CHUNK * 3];     // 3072 floats
        float red[16 * KK * 4];            // 4096 floats
    } sh;

    // Prologue: coalesced staging of this chunk's points (3072 floats).
    {
        const float* src = pts + ((size_t)b * NN + n0) * 3;
        #pragma unroll
        for (int i = tid; i < ROWS_PER_CHUNK * 3; i += 256)
            sh.pts[i] = __ldg(src + i);
    }
    __syncthreads();

    float sg[4] = {0.f, 0.f, 0.f, 0.f};
    float sx[4] = {0.f, 0.f, 0.f, 0.f};
    float sy[4] = {0.f, 0.f, 0.f, 0.f};
    float sz[4] = {0.f, 0.f, 0.f, 0.f};

    #pragma unroll 4
    for (int r = rg; r < ROWS_PER_CHUNK; r += 16) {
        const size_t n = (size_t)b * NN + (size_t)(n0 + r);
        // gamma is streamed once: evict-first so it never thrashes L2
        const float4 g = __ldcs(reinterpret_cast<const float4*>(gam + n * KK + 4 * kg));
        const float px = sh.pts[r * 3 + 0];
        const float py = sh.pts[r * 3 + 1];
        const float pz = sh.pts[r * 3 + 2];
        sg[0] += g.x; sg[1] += g.y; sg[2] += g.z; sg[3] += g.w;
        sx[0] = fmaf(g.x, px, sx[0]); sx[1] = fmaf(g.y, px, sx[1]);
        sx[2] = fmaf(g.z, px, sx[2]); sx[3] = fmaf(g.w, px, sx[3]);
        sy[0] = fmaf(g.x, py, sy[0]); sy[1] = fmaf(g.y, py, sy[1]);
        sy[2] = fmaf(g.z, py, sy[2]); sy[3] = fmaf(g.w, py, sy[3]);
        sz[0] = fmaf(g.x, pz, sz[0]); sz[1] = fmaf(g.y, pz, sz[1]);
        sz[2] = fmaf(g.z, pz, sz[2]); sz[3] = fmaf(g.w, pz, sz[3]);
    }

    // All warps done reading points before the buffer is repurposed.
    __syncthreads();

    // Block reduction across the 16 row-groups: red[rg][k][val]
    #pragma unroll
    for (int j = 0; j < 4; ++j) {
        const int k = 4 * kg + j;
        float* p = &sh.red[(rg * KK + k) * 4];
        p[0] = sg[j]; p[1] = sx[j]; p[2] = sy[j]; p[3] = sz[j];
    }
    __syncthreads();

    // 256 threads == 64 k * 4 vals; tid = k*4 + val
    const int k   = tid >> 2;
    const int val = tid & 3;
    float acc = 0.f;
    #pragma unroll
    for (int r = 0; r < 16; ++r) acc += sh.red[(r * KK + k) * 4 + val];

    g_partials[(((size_t)tsel * BB + b) * CHUNKS + chunk) * (KK * 4) + tid] = acc;
}

// ---------------------------------------------------------------------------
// Stage 2: single-pass moment reduction + weighted Procrustes + 3x3 SVD.
// One block per batch, 64 threads (R7-proven, untouched).
// ---------------------------------------------------------------------------
__device__ __forceinline__ void warp_reduce_n(float* v, int n)
{
    for (int o = 16; o; o >>= 1)
        for (int j = 0; j < n; ++j)
            v[j] += __shfl_xor_sync(0xffffffffu, v[j], o);
}

__global__ void __launch_bounds__(64) stage2_kernel(float* __restrict__ out)
{
    const int b    = blockIdx.x;
    const int k    = threadIdx.x;   // 0..63
    const int wid  = k >> 5;
    const int lane = k & 31;

    float sgx = 0.f, sxx = 0.f, syx = 0.f, szx = 0.f;
    float sgy = 0.f, sxy = 0.f, syy = 0.f, szy = 0.f;
    #pragma unroll
    for (int c = 0; c < CHUNKS; ++c) {
        const float4 px = __ldcg(reinterpret_cast<const float4*>(
            &g_partials[(((size_t)0 * BB + b) * CHUNKS + c) * (KK * 4) + k * 4]));
        sgx += px.x; sxx += px.y; syx += px.z; szx += px.w;
        const float4 py = __ldcg(reinterpret_cast<const float4*>(
            &g_partials[(((size_t)1 * BB + b) * CHUNKS + c) * (KK * 4) + k * 4]));
        sgy += py.x; sxy += py.y; syy += py.z; szy += py.w;
    }

    const float EPSf = 1e-8f;
    const float pix = sgx * (1.0f / (float)NN);
    const float piy = sgy * (1.0f / (float)NN);
    const float rpx = __fdividef(1.0f, pix + EPSf);
    const float rpy = __fdividef(1.0f, piy + EPSf);
    const float mux0 = sxx * rpx, mux1 = syx * rpx, mux2 = szx * rpx;
    const float muy0 = sxy * rpy, muy1 = syy * rpy, muy2 = szy * rpy;
    const float w = pix * piy;

    // --- Single-pass reduction: w, w*mux(3), w*muy(3), w*mux*muy^T(9) = 16 ---
    __shared__ float wsum[2][16];
    {
        float v[16] = {
            w,
            w * mux0, w * mux1, w * mux2,
            w * muy0, w * muy1, w * muy2,
            w * mux0 * muy0, w * mux0 * muy1, w * mux0 * muy2,
            w * mux1 * muy0, w * mux1 * muy1, w * mux1 * muy2,
            w * mux2 * muy0, w * mux2 * muy1, w * mux2 * muy2
        };
        warp_reduce_n(v, 16);
        if (lane == 0)
            #pragma unroll
            for (int j = 0; j < 16; ++j) wsum[wid][j] = v[j];
    }
    __syncthreads();

    if (k == 0) {
        float s[16];
        #pragma unroll
        for (int j = 0; j < 16; ++j) s[j] = wsum[0][j] + wsum[1][j];

        const float wtot = s[0];
        const float ws = __fdividef(1.0f, wtot + EPSf);
        const float cs[3] = { s[1] * ws, s[2] * ws, s[3] * ws };   // c_s
        const float ct[3] = { s[4] * ws, s[5] * ws, s[6] * ws };   // c_t

        // H = S_xy - wtot * c_s c_t^T
        float H[3][3];
        #pragma unroll
        for (int i = 0; i < 3; ++i)
            #pragma unroll
            for (int j = 0; j < 3; ++j)
                H[i][j] = s[7 + i * 3 + j] - wtot * cs[i] * ct[j];

        // Scale H to O(1) for healthy fp32 conditioning in HtH.
        float hmax = 0.f;
        for (int i = 0; i < 3; ++i)
            for (int j = 0; j < 3; ++j) hmax = fmaxf(hmax, fabsf(H[i][j]));
        const float hscale = (hmax > 1e-30f) ? __fdividef(1.0f, hmax) : 1.0f;
        float Hs[3][3];
        for (int i = 0; i < 3; ++i)
            for (int j = 0; j < 3; ++j) Hs[i][j] = H[i][j] * hscale;

        // A = Hs^T Hs (symmetric)
        float A[3][3];
        for (int i = 0; i < 3; ++i)
            for (int j = 0; j < 3; ++j)
                A[i][j] = Hs[0][i] * Hs[0][j] + Hs[1][i] * Hs[1][j] + Hs[2][i] * Hs[2][j];

        float V[3][3] = {{1, 0, 0}, {0, 1, 0}, {0, 0, 1}};
        // Cyclic Jacobi, 5 sweeps. IEEE sqrtf (inf-safe; fast_sqrt NaN'd in R6).
        #pragma unroll 1
        for (int sweep = 0; sweep < 5; ++sweep) {
            const int PQ[3][2] = {{0, 1}, {0, 2}, {1, 2}};
            #pragma unroll
            for (int m = 0; m < 3; ++m) {
                const int p = PQ[m][0], q = PQ[m][1];
                const float apq = A[p][q];
                if (fabsf(apq) < 1e-35f) continue;
                const float tau = __fdividef(A[q][q] - A[p][p], 2.0f * apq);
                float tt = __fdividef(copysignf(1.0f, tau),
                                      fabsf(tau) + sqrtf(1.0f + tau * tau));
                if (!isfinite(tt)) tt = 0.0f;
                const float c = rsqrtf(1.0f + tt * tt);
                const float s2 = tt * c;
                const float app = A[p][p], aqq = A[q][q];
                A[p][p] = app - tt * apq;
                A[q][q] = aqq + tt * apq;
                A[p][q] = A[q][p] = 0.0f;
                const int r = 3 - p - q;
                const float arp = A[r][p], arq = A[r][q];
                A[r][p] = A[p][r] = c * arp - s2 * arq;
                A[r][q] = A[q][r] = s2 * arp + c * arq;
                #pragma unroll
                for (int i = 0; i < 3; ++i) {
                    const float vip = V[i][p], viq = V[i][q];
                    V[i][p] = c * vip - s2 * viq;
                    V[i][q] = s2 * vip + c * viq;
                }
            }
        }

        float eig[3] = {A[0][0], A[1][1], A[2][2]};
        // Sort descending, permuting V columns
        #pragma unroll
        for (int i = 0; i < 2; ++i)
            #pragma unroll
            for (int j = i + 1; j < 3; ++j)
                if (eig[j] > eig[i]) {
                    float tmp = eig[i]; eig[i] = eig[j]; eig[j] = tmp;
                    for (int r = 0; r < 3; ++r) {
                        tmp = V[r][i]; V[r][i] = V[r][j]; V[r][j] = tmp;
                    }
                }

        // U columns: u0 = normalize(Hs v0); u1 = GS(Hs v1); u2 = u0 x u1
        float U[3][3];
        {
            float u0[3], u1[3];
            for (int i = 0; i < 3; ++i)
                u0[i] = Hs[i][0] * V[0][0] + Hs[i][1] * V[1][0] + Hs[i][2] * V[2][0];
            const float nn0 = u0[0] * u0[0] + u0[1] * u0[1] + u0[2] * u0[2];
            if (nn0 > 1e-40f) { const float r = rsqrtf(nn0); u0[0] *= r; u0[1] *= r; u0[2] *= r; }
            else { u0[0] = 1; u0[1] = 0; u0[2] = 0; }

            for (int i = 0; i < 3; ++i)
                u1[i] = Hs[i][0] * V[0][1] + Hs[i][1] * V[1][1] + Hs[i][2] * V[2][1];
            const float d01 = u1[0] * u0[0] + u1[1] * u0[1] + u1[2] * u0[2];
            u1[0] -= d01 * u0[0]; u1[1] -= d01 * u0[1]; u1[2] -= d01 * u0[2];
            const float nn1 = u1[0] * u1[0] + u1[1] * u1[1] + u1[2] * u1[2];
            if (nn1 > 1e-40f) { const float r = rsqrtf(nn1); u1[0] *= r; u1[1] *= r; u1[2] *= r; }
            else {
                // pick any unit vector orthogonal to u0
                const float ax = fabsf(u0[0]), ay = fabsf(u0[1]), az = fabsf(u0[2]);
                float e[3] = {0, 0, 0};
                if (ax <= ay && ax <= az) e[0] = 1;
                else if (ay <= az) e[1] = 1;
                else e[2] = 1;
                u1[0] = u0[1] * e[2] - u0[2] * e[1];
                u1[1] = u0[2] * e[0] - u0[0] * e[2];
                u1[2] = u0[0] * e[1] - u0[1] * e[0];
                const float rn = rsqrtf(u1[0] * u1[0] + u1[1] * u1[1] + u1[2] * u1[2]);
                u1[0] *= rn; u1[1] *= rn; u1[2] *= rn;
            }
            const float u2[3] = { u0[1] * u1[2] - u0[2] * u1[1],
                                  u0[2] * u1[0] - u0[0] * u1[2],
                                  u0[0] * u1[1] - u0[1] * u1[0] };
            for (int i = 0; i < 3; ++i) {
                U[i][0] = u0[i]; U[i][1] = u1[i]; U[i][2] = u2[i];
            }
        }

        const float detV =
            V[0][0] * (V[1][1] * V[2][2] - V[1][2] * V[2][1]) -
            V[0][1] * (V[1][0] * V[2][2] - V[1][2] * V[2][0]) +
            V[0][2] * (V[1][0] * V[2][1] - V[1][1] * V[2][0]);
        const float detU =
            U[0][0] * (U[1][1] * U[2][2] - U[1][2] * U[2][1]) -
            U[0][1] * (U[1][0] * U[2][2] - U[1][2] * U[2][0]) +
            U[0][2] * (U[1][0] * U[2][1] - U[1][1] * U[2][0]);
        const float d = detV * detU;   // det(V U^T)

        // R = V diag(1,1,d) U^T
        float R[3][3];
        for (int i = 0; i < 3; ++i)
            for (int j = 0; j < 3; ++j)
                R[i][j] = V[i][0] * U[j][0] + V[i][1] * U[j][1] + d * V[i][2] * U[j][2];

        // t = c_t - R c_s
        float tv[3];
        for (int i = 0; i < 3; ++i)
            tv[i] = ct[i] - (R[i][0] * cs[0] + R[i][1] * cs[1] + R[i][2] * cs[2]);

        // Output: R (B*9) then t (B*3)
        for (int i = 0; i < 3; ++i)
            for (int j = 0; j < 3; ++j)
                out[b * 9 + i * 3 + j] = R[i][j];
        for (int i = 0; i < 3; ++i)
            out[BB * 9 + b * 3 + i] = tv[i];
    }
}

extern "C" void kernel_launch(void* const* d_in, const int* in_sizes, int n_in,
                              void* d_out, int out_size)
{
    const float* pts_x = (const float*)d_in[0];
    const float* pts_y = (const float*)d_in[1];
    const float* gam_x = (const float*)d_in[2];
    const float* gam_y = (const float*)d_in[3];

    dim3 grid1(CHUNKS, BB, 2);
    stage1_kernel<<<grid1, 256>>>(pts_x, pts_y, gam_x, gam_y);
    stage2_kernel<<<BB, KK>>>((float*)d_out);
}

// round 14
// speedup vs baseline: 1.9420x; 1.0367x over previous
#include <cuda_runtime.h>
#include <math.h>

#define BB 32
#define NN 16384
#define KK 64
#define CHUNKS 16
#define ROWS_PER_CHUNK (NN / CHUNKS)   // 1024

// Deterministic scratch: [tensor][b][chunk][k][4]  (sg, sx, sy, sz)
__device__ float g_partials[2 * BB * CHUNKS * KK * 4];

// ---------------------------------------------------------------------------
// Stage 1: per-chunk weighted reductions (pure HBM streaming).
// R3/R7-proven config verbatim: launch_bounds(256,8), unroll 4, __ldcs.
// ---------------------------------------------------------------------------
__global__ void __launch_bounds__(256, 8) stage1_kernel(
    const float* __restrict__ pts_x, const float* __restrict__ pts_y,
    const float* __restrict__ gam_x, const float* __restrict__ gam_y)
{
    const int chunk = blockIdx.x;
    const int b     = blockIdx.y;
    const int tsel  = blockIdx.z;
    const float* __restrict__ pts = tsel ? pts_y : pts_x;
    const float* __restrict__ gam = tsel ? gam_y : gam_x;

    const int tid = threadIdx.x;
    const int kg  = tid & 15;   // k4 group
    const int rg  = tid >> 4;   // row group 0..15

    float sg[4] = {0.f, 0.f, 0.f, 0.f};
    float sx[4] = {0.f, 0.f, 0.f, 0.f};
    float sy[4] = {0.f, 0.f, 0.f, 0.f};
    float sz[4] = {0.f, 0.f, 0.f, 0.f};

    const int n0 = chunk * ROWS_PER_CHUNK;

    #pragma unroll 4
    for (int r = rg; r < ROWS_PER_CHUNK; r += 16) {
        const size_t n = (size_t)b * NN + (size_t)(n0 + r);
        // gamma is streamed once: evict-first so it never thrashes L2
        const float4 g = __ldcs(reinterpret_cast<const float4*>(gam + n * KK + 4 * kg));
        const float px = __ldg(pts + n * 3 + 0);
        const float py = __ldg(pts + n * 3 + 1);
        const float pz = __ldg(pts + n * 3 + 2);
        sg[0] += g.x; sg[1] += g.y; sg[2] += g.z; sg[3] += g.w;
        sx[0] = fmaf(g.x, px, sx[0]); sx[1] = fmaf(g.y, px, sx[1]);
        sx[2] = fmaf(g.z, px, sx[2]); sx[3] = fmaf(g.w, px, sx[3]);
        sy[0] = fmaf(g.x, py, sy[0]); sy[1] = fmaf(g.y, py, sy[1]);
        sy[2] = fmaf(g.z, py, sy[2]); sy[3] = fmaf(g.w, py, sy[3]);
        sz[0] = fmaf(g.x, pz, sz[0]); sz[1] = fmaf(g.y, pz, sz[1]);
        sz[2] = fmaf(g.z, pz, sz[2]); sz[3] = fmaf(g.w, pz, sz[3]);
    }

    // Block reduction across the 16 row-groups: smem[rg][k][val]
    __shared__ float smem[16 * KK * 4];
    #pragma unroll
    for (int j = 0; j < 4; ++j) {
        const int k = 4 * kg + j;
        float* p = &smem[(rg * KK + k) * 4];
        p[0] = sg[j]; p[1] = sx[j]; p[2] = sy[j]; p[3] = sz[j];
    }
    __syncthreads();

    // 256 threads == 64 k * 4 vals; tid = k*4 + val
    const int k   = tid >> 2;
    const int val = tid & 3;
    float acc = 0.f;
    #pragma unroll
    for (int r = 0; r < 16; ++r) acc += smem[(r * KK + k) * 4 + val];

    g_partials[(((size_t)tsel * BB + b) * CHUNKS + chunk) * (KK * 4) + tid] = acc;
}

// ---------------------------------------------------------------------------
// Stage 2: 256 threads/block; chunk-split loading (8 float4/thread instead of
// 32) to collapse the load-latency exposure, then single-pass moment
// reduction + weighted Procrustes + 3x3 SVD (R7 math, clamped fast sqrt).
// ---------------------------------------------------------------------------
__device__ __forceinline__ void warp_reduce_n(float* v, int n)
{
    for (int o = 16; o; o >>= 1)
        for (int j = 0; j < n; ++j)
            v[j] += __shfl_xor_sync(0xffffffffu, v[j], o);
}

__global__ void __launch_bounds__(256) stage2_kernel(float* __restrict__ out)
{
    const int b   = blockIdx.x;
    const int tid = threadIdx.x;
    const int cg  = tid >> 6;    // chunk group 0..3 (4 chunks each)
    const int k   = tid & 63;    // component index

    // Phase 1: each thread loads 4 chunks of both tensors (8 float4 total).
    float a[8] = {0.f, 0.f, 0.f, 0.f, 0.f, 0.f, 0.f, 0.f};
    #pragma unroll
    for (int ci = 0; ci < 4; ++ci) {
        const int c = cg * 4 + ci;
        const float4 px = __ldcg(reinterpret_cast<const float4*>(
            &g_partials[(((size_t)0 * BB + b) * CHUNKS + c) * (KK * 4) + k * 4]));
        a[0] += px.x; a[1] += px.y; a[2] += px.z; a[3] += px.w;
        const float4 py = __ldcg(reinterpret_cast<const float4*>(
            &g_partials[(((size_t)1 * BB + b) * CHUNKS + c) * (KK * 4) + k * 4]));
        a[4] += py.x; a[5] += py.y; a[6] += py.z; a[7] += py.w;
    }

    __shared__ float red[4][KK][9];   // pad 8->9 to dodge bank conflicts
    #pragma unroll
    for (int j = 0; j < 8; ++j) red[cg][k][j] = a[j];
    __syncthreads();

    __shared__ float wsum[2][16];

    // Phase 2: threads 0..63 combine the 4 chunk-groups and run the
    // 16-value moment reduction (2 warps).
    if (tid < KK) {
        const int wid  = tid >> 5;
        const int lane = tid & 31;

        float sgx = 0.f, sxx = 0.f, syx = 0.f, szx = 0.f;
        float sgy = 0.f, sxy = 0.f, syy = 0.f, szy = 0.f;
        #pragma unroll
        for (int g = 0; g < 4; ++g) {
            sgx += red[g][tid][0]; sxx += red[g][tid][1];
            syx += red[g][tid][2]; szx += red[g][tid][3];
            sgy += red[g][tid][4]; sxy += red[g][tid][5];
            syy += red[g][tid][6]; szy += red[g][tid][7];
        }

        const float EPSf = 1e-8f;
        const float pix = sgx * (1.0f / (float)NN);
        const float piy = sgy * (1.0f / (float)NN);
        const float rpx = __fdividef(1.0f, pix + EPSf);
        const float rpy = __fdividef(1.0f, piy + EPSf);
        const float mux0 = sxx * rpx, mux1 = syx * rpx, mux2 = szx * rpx;
        const float muy0 = sxy * rpy, muy1 = syy * rpy, muy2 = szy * rpy;
        const float w = pix * piy;

        float v[16] = {
            w,
            w * mux0, w * mux1, w * mux2,
            w * muy0, w * muy1, w * muy2,
            w * mux0 * muy0, w * mux0 * muy1, w * mux0 * muy2,
            w * mux1 * muy0, w * mux1 * muy1, w * mux1 * muy2,
            w * mux2 * muy0, w * mux2 * muy1, w * mux2 * muy2
        };
        warp_reduce_n(v, 16);
        if (lane == 0)
            #pragma unroll
            for (int j = 0; j < 16; ++j) wsum[wid][j] = v[j];
    }
    __syncthreads();

    if (tid == 0) {
        const float EPSf = 1e-8f;
        float s[16];
        #pragma unroll
        for (int j = 0; j < 16; ++j) s[j] = wsum[0][j] + wsum[1][j];

        const float wtot = s[0];
        const float ws = __fdividef(1.0f, wtot + EPSf);
        const float cs[3] = { s[1] * ws, s[2] * ws, s[3] * ws };   // c_s
        const float ct[3] = { s[4] * ws, s[5] * ws, s[6] * ws };   // c_t

        // H = S_xy - wtot * c_s c_t^T
        float H[3][3];
        #pragma unroll
        for (int i = 0; i < 3; ++i)
            #pragma unroll
            for (int j = 0; j < 3; ++j)
                H[i][j] = s[7 + i * 3 + j] - wtot * cs[i] * ct[j];

        // Scale H to O(1) for healthy fp32 conditioning in HtH.
        float hmax = 0.f;
        for (int i = 0; i < 3; ++i)
            for (int j = 0; j < 3; ++j) hmax = fmaxf(hmax, fabsf(H[i][j]));
        const float hscale = (hmax > 1e-30f) ? __fdividef(1.0f, hmax) : 1.0f;
        float Hs[3][3];
        for (int i = 0; i < 3; ++i)
            for (int j = 0; j < 3; ++j) Hs[i][j] = H[i][j] * hscale;

        // A = Hs^T Hs (symmetric)
        float A[3][3];
        for (int i = 0; i < 3; ++i)
            for (int j = 0; j < 3; ++j)
                A[i][j] = Hs[0][i] * Hs[0][j] + Hs[1][i] * Hs[1][j] + Hs[2][i] * Hs[2][j];

        float V[3][3] = {{1, 0, 0}, {0, 1, 0}, {0, 0, 1}};
        // Cyclic Jacobi, 5 sweeps. tau clamped so 1+tau^2 stays finite,
        // which makes x*rsqrtf(x) a safe fast sqrt (R6's NaN was tau=inf).
        #pragma unroll 1
        for (int sweep = 0; sweep < 5; ++sweep) {
            const int PQ[3][2] = {{0, 1}, {0, 2}, {1, 2}};
            #pragma unroll
            for (int m = 0; m < 3; ++m) {
                const int p = PQ[m][0], q = PQ[m][1];
                const float apq = A[p][q];
                if (fabsf(apq) < 1e-35f) continue;
                const float tau_raw = __fdividef(A[q][q] - A[p][p], 2.0f * apq);
                const float atau = fminf(fabsf(tau_raw), 1e18f);   // finite tau^2
                const float x = 1.0f + atau * atau;
                const float sq = x * rsqrtf(x);                    // fast sqrt
                float tt = __fdividef(copysignf(1.0f, tau_raw), atau + sq);
                if (!isfinite(tt)) tt = 0.0f;
                const float c = rsqrtf(1.0f + tt * tt);
                const float s2 = tt * c;
                const float app = A[p][p], aqq = A[q][q];
                A[p][p] = app - tt * apq;
                A[q][q] = aqq + tt * apq;
                A[p][q] = A[q][p] = 0.0f;
                const int r = 3 - p - q;
                const float arp = A[r][p], arq = A[r][q];
                A[r][p] = A[p][r] = c * arp - s2 * arq;
                A[r][q] = A[q][r] = s2 * arp + c * arq;
                #pragma unroll
                for (int i = 0; i < 3; ++i) {
                    const float vip = V[i][p], viq = V[i][q];
                    V[i][p] = c * vip - s2 * viq;
                    V[i][q] = s2 * vip + c * viq;
                }
            }
        }

        float eig[3] = {A[0][0], A[1][1], A[2][2]};
        // Sort descending, permuting V columns
        #pragma unroll
        for (int i = 0; i < 2; ++i)
            #pragma unroll
            for (int j = i + 1; j < 3; ++j)
                if (eig[j] > eig[i]) {
                    float tmp = eig[i]; eig[i] = eig[j]; eig[j] = tmp;
                    for (int r = 0; r < 3; ++r) {
                        tmp = V[r][i]; V[r][i] = V[r][j]; V[r][j] = tmp;
                    }
                }

        // U columns: u0 = normalize(Hs v0); u1 = GS(Hs v1); u2 = u0 x u1
        float U[3][3];
        {
            float u0[3], u1[3];
            for (int i = 0; i < 3; ++i)
                u0[i] = Hs[i][0] * V[0][0] + Hs[i][1] * V[1][0] + Hs[i][2] * V[2][0];
            const float nn0 = u0[0] * u0[0] + u0[1] * u0[1] + u0[2] * u0[2];
            if (nn0 > 1e-40f) { const float r = rsqrtf(nn0); u0[0] *= r; u0[1] *= r; u0[2] *= r; }
            else { u0[0] = 1; u0[1] = 0; u0[2] = 0; }

            for (int i = 0; i < 3; ++i)
                u1[i] = Hs[i][0] * V[0][1] + Hs[i][1] * V[1][1] + Hs[i][2] * V[2][1];
            const float d01 = u1[0] * u0[0] + u1[1] * u0[1] + u1[2] * u0[2];
            u1[0] -= d01 * u0[0]; u1[1] -= d01 * u0[1]; u1[2] -= d01 * u0[2];
            const float nn1 = u1[0] * u1[0] + u1[1] * u1[1] + u1[2] * u1[2];
            if (nn1 > 1e-40f) { const float r = rsqrtf(nn1); u1[0] *= r; u1[1] *= r; u1[2] *= r; }
            else {
                // pick any unit vector orthogonal to u0
                const float ax = fabsf(u0[0]), ay = fabsf(u0[1]), az = fabsf(u0[2]);
                float e[3] = {0, 0, 0};
                if (ax <= ay && ax <= az) e[0] = 1;
                else if (ay <= az) e[1] = 1;
                else e[2] = 1;
                u1[0] = u0[1] * e[2] - u0[2] * e[1];
                u1[1] = u0[2] * e[0] - u0[0] * e[2];
                u1[2] = u0[0] * e[1] - u0[1] * e[0];
                const float rn = rsqrtf(u1[0] * u1[0] + u1[1] * u1[1] + u1[2] * u1[2]);
                u1[0] *= rn; u1[1] *= rn; u1[2] *= rn;
            }
            const float u2[3] = { u0[1] * u1[2] - u0[2] * u1[1],
                                  u0[2] * u1[0] - u0[0] * u1[2],
                                  u0[0] * u1[1] - u0[1] * u1[0] };
            for (int i = 0; i < 3; ++i) {
                U[i][0] = u0[i]; U[i][1] = u1[i]; U[i][2] = u2[i];
            }
        }

        const float detV =
            V[0][0] * (V[1][1] * V[2][2] - V[1][2] * V[2][1]) -
            V[0][1] * (V[1][0] * V[2][2] - V[1][2] * V[2][0]) +
            V[0][2] * (V[1][0] * V[2][1] - V[1][1] * V[2][0]);
        const float detU =
            U[0][0] * (U[1][1] * U[2][2] - U[1][2] * U[2][1]) -
            U[0][1] * (U[1][0] * U[2][2] - U[1][2] * U[2][0]) +
            U[0][2] * (U[1][0] * U[2][1] - U[1][1] * U[2][0]);
        const float d = detV * detU;   // det(V U^T)

        // R = V diag(1,1,d) U^T
        float R[3][3];
        for (int i = 0; i < 3; ++i)
            for (int j = 0; j < 3; ++j)
                R[i][j] = V[i][0] * U[j][0] + V[i][1] * U[j][1] + d * V[i][2] * U[j][2];

        // t = c_t - R c_s
        float tv[3];
        for (int i = 0; i < 3; ++i)
            tv[i] = ct[i] - (R[i][0] * cs[0] + R[i][1] * cs[1] + R[i][2] * cs[2]);

        // Output: R (B*9) then t (B*3)
        for (int i = 0; i < 3; ++i)
            for (int j = 0; j < 3; ++j)
                out[b * 9 + i * 3 + j] = R[i][j];
        for (int i = 0; i < 3; ++i)
            out[BB * 9 + b * 3 + i] = tv[i];
    }
}

extern "C" void kernel_launch(void* const* d_in, const int* in_sizes, int n_in,
                              void* d_out, int out_size)
{
    const float* pts_x = (const float*)d_in[0];
    const float* pts_y = (const float*)d_in[1];
    const float* gam_x = (const float*)d_in[2];
    const float* gam_y = (const float*)d_in[3];

    dim3 grid1(CHUNKS, BB, 2);
    stage1_kernel<<<grid1, 256>>>(pts_x, pts_y, gam_x, gam_y);
    stage2_kernel<<<BB, 256>>>((float*)d_out);
}

// round 15
// speedup vs baseline: 1.9524x; 1.0054x over previous
#include <cuda_runtime.h>
#include <math.h>

#define BB 32
#define NN 16384
#define KK 64
#define CHUNKS 16
#define ROWS_PER_CHUNK (NN / CHUNKS)   // 1024

// Deterministic scratch: [tensor][b][chunk][k][4]  (sg, sx, sy, sz)
__device__ float g_partials[2 * BB * CHUNKS * KK * 4];

// ---------------------------------------------------------------------------
// Stage 1: per-chunk weighted reductions (pure HBM streaming).
// R3/R7 config with launch_bounds(256,7): 1036 slots >= 1024 blocks (still a
// single wave, same residency), but reg cap 32->36 lets ptxas front-batch the
// unrolled gamma loads.
// ---------------------------------------------------------------------------
__global__ void __launch_bounds__(256, 7) stage1_kernel(
    const float* __restrict__ pts_x, const float* __restrict__ pts_y,
    const float* __restrict__ gam_x, const float* __restrict__ gam_y)
{
    const int chunk = blockIdx.x;
    const int b     = blockIdx.y;
    const int tsel  = blockIdx.z;
    const float* __restrict__ pts = tsel ? pts_y : pts_x;
    const float* __restrict__ gam = tsel ? gam_y : gam_x;

    const int tid = threadIdx.x;
    const int kg  = tid & 15;   // k4 group
    const int rg  = tid >> 4;   // row group 0..15

    float sg[4] = {0.f, 0.f, 0.f, 0.f};
    float sx[4] = {0.f, 0.f, 0.f, 0.f};
    float sy[4] = {0.f, 0.f, 0.f, 0.f};
    float sz[4] = {0.f, 0.f, 0.f, 0.f};

    const int n0 = chunk * ROWS_PER_CHUNK;

    #pragma unroll 4
    for (int r = rg; r < ROWS_PER_CHUNK; r += 16) {
        const size_t n = (size_t)b * NN + (size_t)(n0 + r);
        // gamma is streamed once: evict-first so it never thrashes L2
        const float4 g = __ldcs(reinterpret_cast<const float4*>(gam + n * KK + 4 * kg));
        const float px = __ldg(pts + n * 3 + 0);
        const float py = __ldg(pts + n * 3 + 1);
        const float pz = __ldg(pts + n * 3 + 2);
        sg[0] += g.x; sg[1] += g.y; sg[2] += g.z; sg[3] += g.w;
        sx[0] = fmaf(g.x, px, sx[0]); sx[1] = fmaf(g.y, px, sx[1]);
        sx[2] = fmaf(g.z, px, sx[2]); sx[3] = fmaf(g.w, px, sx[3]);
        sy[0] = fmaf(g.x, py, sy[0]); sy[1] = fmaf(g.y, py, sy[1]);
        sy[2] = fmaf(g.z, py, sy[2]); sy[3] = fmaf(g.w, py, sy[3]);
        sz[0] = fmaf(g.x, pz, sz[0]); sz[1] = fmaf(g.y, pz, sz[1]);
        sz[2] = fmaf(g.z, pz, sz[2]); sz[3] = fmaf(g.w, pz, sz[3]);
    }

    // Block reduction across the 16 row-groups: smem[rg][k][val]
    __shared__ float smem[16 * KK * 4];
    #pragma unroll
    for (int j = 0; j < 4; ++j) {
        const int k = 4 * kg + j;
        float* p = &smem[(rg * KK + k) * 4];
        p[0] = sg[j]; p[1] = sx[j]; p[2] = sy[j]; p[3] = sz[j];
    }
    __syncthreads();

    // 256 threads == 64 k * 4 vals; tid = k*4 + val
    const int k   = tid >> 2;
    const int val = tid & 3;
    float acc = 0.f;
    #pragma unroll
    for (int r = 0; r < 16; ++r) acc += smem[(r * KK + k) * 4 + val];

    g_partials[(((size_t)tsel * BB + b) * CHUNKS + chunk) * (KK * 4) + tid] = acc;
}

// ---------------------------------------------------------------------------
// Stage 2: 256 threads/block; chunk-split loading (8 float4/thread), then
// single-pass moment reduction + weighted Procrustes + 3x3 SVD (4 sweeps).
// ---------------------------------------------------------------------------
__device__ __forceinline__ void warp_reduce_n(float* v, int n)
{
    for (int o = 16; o; o >>= 1)
        for (int j = 0; j < n; ++j)
            v[j] += __shfl_xor_sync(0xffffffffu, v[j], o);
}

__global__ void __launch_bounds__(256) stage2_kernel(float* __restrict__ out)
{
    const int b   = blockIdx.x;
    const int tid = threadIdx.x;
    const int cg  = tid >> 6;    // chunk group 0..3 (4 chunks each)
    const int k   = tid & 63;    // component index

    // Phase 1: each thread loads 4 chunks of both tensors (8 float4 total).
    float a[8] = {0.f, 0.f, 0.f, 0.f, 0.f, 0.f, 0.f, 0.f};
    #pragma unroll
    for (int ci = 0; ci < 4; ++ci) {
        const int c = cg * 4 + ci;
        const float4 px = __ldcg(reinterpret_cast<const float4*>(
            &g_partials[(((size_t)0 * BB + b) * CHUNKS + c) * (KK * 4) + k * 4]));
        a[0] += px.x; a[1] += px.y; a[2] += px.z; a[3] += px.w;
        const float4 py = __ldcg(reinterpret_cast<const float4*>(
            &g_partials[(((size_t)1 * BB + b) * CHUNKS + c) * (KK * 4) + k * 4]));
        a[4] += py.x; a[5] += py.y; a[6] += py.z; a[7] += py.w;
    }

    __shared__ float red[4][KK][9];   // pad 8->9 to dodge bank conflicts
    #pragma unroll
    for (int j = 0; j < 8; ++j) red[cg][k][j] = a[j];
    __syncthreads();

    __shared__ float wsum[2][16];

    // Phase 2: threads 0..63 combine the 4 chunk-groups and run the
    // 16-value moment reduction (2 warps).
    if (tid < KK) {
        const int wid  = tid >> 5;
        const int lane = tid & 31;

        float sgx = 0.f, sxx = 0.f, syx = 0.f, szx = 0.f;
        float sgy = 0.f, sxy = 0.f, syy = 0.f, szy = 0.f;
        #pragma unroll
        for (int g = 0; g < 4; ++g) {
            sgx += red[g][tid][0]; sxx += red[g][tid][1];
            syx += red[g][tid][2]; szx += red[g][tid][3];
            sgy += red[g][tid][4]; sxy += red[g][tid][5];
            syy += red[g][tid][6]; szy += red[g][tid][7];
        }

        const float EPSf = 1e-8f;
        const float pix = sgx * (1.0f / (float)NN);
        const float piy = sgy * (1.0f / (float)NN);
        const float rpx = __fdividef(1.0f, pix + EPSf);
        const float rpy = __fdividef(1.0f, piy + EPSf);
        const float mux0 = sxx * rpx, mux1 = syx * rpx, mux2 = szx * rpx;
        const float muy0 = sxy * rpy, muy1 = syy * rpy, muy2 = szy * rpy;
        const float w = pix * piy;

        float v[16] = {
            w,
            w * mux0, w * mux1, w * mux2,
            w * muy0, w * muy1, w * muy2,
            w * mux0 * muy0, w * mux0 * muy1, w * mux0 * muy2,
            w * mux1 * muy0, w * mux1 * muy1, w * mux1 * muy2,
            w * mux2 * muy0, w * mux2 * muy1, w * mux2 * muy2
        };
        warp_reduce_n(v, 16);
        if (lane == 0)
            #pragma unroll
            for (int j = 0; j < 16; ++j) wsum[wid][j] = v[j];
    }
    __syncthreads();

    if (tid == 0) {
        const float EPSf = 1e-8f;
        float s[16];
        #pragma unroll
        for (int j = 0; j < 16; ++j) s[j] = wsum[0][j] + wsum[1][j];

        const float wtot = s[0];
        const float ws = __fdividef(1.0f, wtot + EPSf);
        const float cs[3] = { s[1] * ws, s[2] * ws, s[3] * ws };   // c_s
        const float ct[3] = { s[4] * ws, s[5] * ws, s[6] * ws };   // c_t

        // H = S_xy - wtot * c_s c_t^T
        float H[3][3];
        #pragma unroll
        for (int i = 0; i < 3; ++i)
            #pragma unroll
            for (int j = 0; j < 3; ++j)
                H[i][j] = s[7 + i * 3 + j] - wtot * cs[i] * ct[j];

        // Scale H to O(1) for healthy fp32 conditioning in HtH.
        float hmax = 0.f;
        for (int i = 0; i < 3; ++i)
            for (int j = 0; j < 3; ++j) hmax = fmaxf(hmax, fabsf(H[i][j]));
        const float hscale = (hmax > 1e-30f) ? __fdividef(1.0f, hmax) : 1.0f;
        float Hs[3][3];
        for (int i = 0; i < 3; ++i)
            for (int j = 0; j < 3; ++j) Hs[i][j] = H[i][j] * hscale;

        // A = Hs^T Hs (symmetric)
        float A[3][3];
        for (int i = 0; i < 3; ++i)
            for (int j = 0; j < 3; ++j)
                A[i][j] = Hs[0][i] * Hs[0][j] + Hs[1][i] * Hs[1][j] + Hs[2][i] * Hs[2][j];

        float V[3][3] = {{1, 0, 0}, {0, 1, 0}, {0, 0, 1}};
        // Cyclic Jacobi, 4 sweeps (12 rotations; quadratic convergence).
        // tau clamped so 1+tau^2 stays finite -> x*rsqrtf(x) is a safe sqrt.
        #pragma unroll 1
        for (int sweep = 0; sweep < 4; ++sweep) {
            const int PQ[3][2] = {{0, 1}, {0, 2}, {1, 2}};
            #pragma unroll
            for (int m = 0; m < 3; ++m) {
                const int p = PQ[m][0], q = PQ[m][1];
                const float apq = A[p][q];
                if (fabsf(apq) < 1e-35f) continue;
                const float tau_raw = __fdividef(A[q][q] - A[p][p], 2.0f * apq);
                const float atau = fminf(fabsf(tau_raw), 1e18f);   // finite tau^2
                const float x = 1.0f + atau * atau;
                const float sq = x * rsqrtf(x);                    // fast sqrt
                float tt = __fdividef(copysignf(1.0f, tau_raw), atau + sq);
                if (!isfinite(tt)) tt = 0.0f;
                const float c = rsqrtf(1.0f + tt * tt);
                const float s2 = tt * c;
                const float app = A[p][p], aqq = A[q][q];
                A[p][p] = app - tt * apq;
                A[q][q] = aqq + tt * apq;
                A[p][q] = A[q][p] = 0.0f;
                const int r = 3 - p - q;
                const float arp = A[r][p], arq = A[r][q];
                A[r][p] = A[p][r] = c * arp - s2 * arq;
                A[r][q] = A[q][r] = s2 * arp + c * arq;
                #pragma unroll
                for (int i = 0; i < 3; ++i) {
                    const float vip = V[i][p], viq = V[i][q];
                    V[i][p] = c * vip - s2 * viq;
                    V[i][q] = s2 * vip + c * viq;
                }
            }
        }

        float eig[3] = {A[0][0], A[1][1], A[2][2]};
        // Sort descending, permuting V columns
        #pragma unroll
        for (int i = 0; i < 2; ++i)
            #pragma unroll
            for (int j = i + 1; j < 3; ++j)
                if (eig[j] > eig[i]) {
                    float tmp = eig[i]; eig[i] = eig[j]; eig[j] = tmp;
                    for (int r = 0; r < 3; ++r) {
                        tmp = V[r][i]; V[r][i] = V[r][j]; V[r][j] = tmp;
                    }
                }

        // U columns: u0 = normalize(Hs v0); u1 = GS(Hs v1); u2 = u0 x u1
        float U[3][3];
        {
            float u0[3], u1[3];
            for (int i = 0; i < 3; ++i)
                u0[i] = Hs[i][0] * V[0][0] + Hs[i][1] * V[1][0] + Hs[i][2] * V[2][0];
            const float nn0 = u0[0] * u0[0] + u0[1] * u0[1] + u0[2] * u0[2];
            if (nn0 > 1e-40f) { const float r = rsqrtf(nn0); u0[0] *= r; u0[1] *= r; u0[2] *= r; }
            else { u0[0] = 1; u0[1] = 0; u0[2] = 0; }

            for (int i = 0; i < 3; ++i)
                u1[i] = Hs[i][0] * V[0][1] + Hs[i][1] * V[1][1] + Hs[i][2] * V[2][1];
            const float d01 = u1[0] * u0[0] + u1[1] * u0[1] + u1[2] * u0[2];
            u1[0] -= d01 * u0[0]; u1[1] -= d01 * u0[1]; u1[2] -= d01 * u0[2];
            const float nn1 = u1[0] * u1[0] + u1[1] * u1[1] + u1[2] * u1[2];
            if (nn1 > 1e-40f) { const float r = rsqrtf(nn1); u1[0] *= r; u1[1] *= r; u1[2] *= r; }
            else {
                // pick any unit vector orthogonal to u0
                const float ax = fabsf(u0[0]), ay = fabsf(u0[1]), az = fabsf(u0[2]);
                float e[3] = {0, 0, 0};
                if (ax <= ay && ax <= az) e[0] = 1;
                else if (ay <= az) e[1] = 1;
                else e[2] = 1;
                u1[0] = u0[1] * e[2] - u0[2] * e[1];
                u1[1] = u0[2] * e[0] - u0[0] * e[2];
                u1[2] = u0[0] * e[1] - u0[1] * e[0];
                const float rn = rsqrtf(u1[0] * u1[0] + u1[1] * u1[1] + u1[2] * u1[2]);
                u1[0] *= rn; u1[1] *= rn; u1[2] *= rn;
            }
            const float u2[3] = { u0[1] * u1[2] - u0[2] * u1[1],
                                  u0[2] * u1[0] - u0[0] * u1[2],
                                  u0[0] * u1[1] - u0[1] * u1[0] };
            for (int i = 0; i < 3; ++i) {
                U[i][0] = u0[i]; U[i][1] = u1[i]; U[i][2] = u2[i];
            }
        }

        const float detV =
            V[0][0] * (V[1][1] * V[2][2] - V[1][2] * V[2][1]) -
            V[0][1] * (V[1][0] * V[2][2] - V[1][2] * V[2][0]) +
            V[0][2] * (V[1][0] * V[2][1] - V[1][1] * V[2][0]);
        const float detU =
            U[0][0] * (U[1][1] * U[2][2] - U[1][2] * U[2][1]) -
            U[0][1] * (U[1][0] * U[2][2] - U[1][2] * U[2][0]) +
            U[0][2] * (U[1][0] * U[2][1] - U[1][1] * U[2][0]);
        const float d = detV * detU;   // det(V U^T)

        // R = V diag(1,1,d) U^T
        float R[3][3];
        for (int i = 0; i < 3; ++i)
            for (int j = 0; j < 3; ++j)
                R[i][j] = V[i][0] * U[j][0] + V[i][1] * U[j][1] + d * V[i][2] * U[j][2];

        // t = c_t - R c_s
        float tv[3];
        for (int i = 0; i < 3; ++i)
            tv[i] = ct[i] - (R[i][0] * cs[0] + R[i][1] * cs[1] + R[i][2] * cs[2]);

        // Output: R (B*9) then t (B*3)
        for (int i = 0; i < 3; ++i)
            for (int j = 0; j < 3; ++j)
                out[b * 9 + i * 3 + j] = R[i][j];
        for (int i = 0; i < 3; ++i)
            out[BB * 9 + b * 3 + i] = tv[i];
    }
}

extern "C" void kernel_launch(void* const* d_in, const int* in_sizes, int n_in,
                              void* d_out, int out_size)
{
    const float* pts_x = (const float*)d_in[0];
    const float* pts_y = (const float*)d_in[1];
    const float* gam_x = (const float*)d_in[2];
    const float* gam_y = (const float*)d_in[3];

    dim3 grid1(CHUNKS, BB, 2);
    stage1_kernel<<<grid1, 256>>>(pts_x, pts_y, gam_x, gam_y);
    stage2_kernel<<<BB, 256>>>((float*)d_out);
}

// round 16
// speedup vs baseline: 1.9535x; 1.0006x over previous
#include <cuda_runtime.h>
#include <math.h>

#define BB 32
#define NN 16384
#define KK 64
#define CHUNKS 16
#define ROWS_PER_CHUNK (NN / CHUNKS)   // 1024

typedef unsigned long long u64;

// Deterministic scratch: [tensor][b][chunk][k][4]  (sg, sx, sy, sz)
__device__ float g_partials[2 * BB * CHUNKS * KK * 4];

// ---- packed f32x2 helpers (sm_103a; ptxas never auto-fuses these) ----
__device__ __forceinline__ u64 fma2(u64 a, u64 b, u64 c) {
    u64 d;
    asm("fma.rn.f32x2 %0, %1, %2, %3;" : "=l"(d) : "l"(a), "l"(b), "l"(c));
    return d;
}
__device__ __forceinline__ u64 add2(u64 a, u64 b) {
    u64 d;
    asm("add.rn.f32x2 %0, %1, %2;" : "=l"(d) : "l"(a), "l"(b));
    return d;
}
__device__ __forceinline__ u64 bcast2(float x) {
    u64 d;
    asm("mov.b64 %0, {%1, %2};" : "=l"(d) : "f"(x), "f"(x));
    return d;
}
__device__ __forceinline__ void unpack2(u64 v, float& lo, float& hi) {
    asm("mov.b64 {%0, %1}, %2;" : "=f"(lo), "=f"(hi) : "l"(v));
}

// ---------------------------------------------------------------------------
// Stage 1: per-chunk weighted reductions (HBM streaming).
// Hot loop in packed f32x2: gamma LDG.128 lands as double2 (two f32x2 pairs,
// zero pack cost); 8 f32x2 ops replace 20 scalar FMA-pipe ops per iteration.
// ---------------------------------------------------------------------------
__global__ void __launch_bounds__(256, 7) stage1_kernel(
    const float* __restrict__ pts_x, const float* __restrict__ pts_y,
    const float* __restrict__ gam_x, const float* __restrict__ gam_y)
{
    const int chunk = blockIdx.x;
    const int b     = blockIdx.y;
    const int tsel  = blockIdx.z;
    const float* __restrict__ pts = tsel ? pts_y : pts_x;
    const float* __restrict__ gam = tsel ? gam_y : gam_x;

    const int tid = threadIdx.x;
    const int kg  = tid & 15;   // k4 group
    const int rg  = tid >> 4;   // row group 0..15

    u64 sg01 = 0ull, sg23 = 0ull;   // bit pattern 0 == (0.0f, 0.0f)
    u64 sx01 = 0ull, sx23 = 0ull;
    u64 sy01 = 0ull, sy23 = 0ull;
    u64 sz01 = 0ull, sz23 = 0ull;

    const int n0 = chunk * ROWS_PER_CHUNK;

    #pragma unroll 4
    for (int r = rg; r < ROWS_PER_CHUNK; r += 16) {
        const size_t n = (size_t)b * NN + (size_t)(n0 + r);
        // gamma streamed once (evict-first); one LDG.128 viewed as 2 f32x2
        const double2 gd = __ldcs(reinterpret_cast<const double2*>(gam + n * KK + 4 * kg));
        const u64 g01 = __double_as_longlong(gd.x);
        const u64 g23 = __double_as_longlong(gd.y);
        const u64 pxx = bcast2(__ldg(pts + n * 3 + 0));
        const u64 pyy = bcast2(__ldg(pts + n * 3 + 1));
        const u64 pzz = bcast2(__ldg(pts + n * 3 + 2));
        sg01 = add2(sg01, g01);       sg23 = add2(sg23, g23);
        sx01 = fma2(g01, pxx, sx01);  sx23 = fma2(g23, pxx, sx23);
        sy01 = fma2(g01, pyy, sy01);  sy23 = fma2(g23, pyy, sy23);
        sz01 = fma2(g01, pzz, sz01);  sz23 = fma2(g23, pzz, sz23);
    }

    // Unpack to scalars (identical per-k accumulation order as scalar code)
    float sg[4], sx[4], sy[4], sz[4];
    unpack2(sg01, sg[0], sg[1]); unpack2(sg23, sg[2], sg[3]);
    unpack2(sx01, sx[0], sx[1]); unpack2(sx23, sx[2], sx[3]);
    unpack2(sy01, sy[0], sy[1]); unpack2(sy23, sy[2], sy[3]);
    unpack2(sz01, sz[0], sz[1]); unpack2(sz23, sz[2], sz[3]);

    // Block reduction across the 16 row-groups: smem[rg][k][val]
    __shared__ float smem[16 * KK * 4];
    #pragma unroll
    for (int j = 0; j < 4; ++j) {
        const int k = 4 * kg + j;
        float* p = &smem[(rg * KK + k) * 4];
        p[0] = sg[j]; p[1] = sx[j]; p[2] = sy[j]; p[3] = sz[j];
    }
    __syncthreads();

    // 256 threads == 64 k * 4 vals; tid = k*4 + val
    const int k   = tid >> 2;
    const int val = tid & 3;
    float acc = 0.f;
    #pragma unroll
    for (int r = 0; r < 16; ++r) acc += smem[(r * KK + k) * 4 + val];

    g_partials[(((size_t)tsel * BB + b) * CHUNKS + chunk) * (KK * 4) + tid] = acc;
}

// ---------------------------------------------------------------------------
// Stage 2: 256 threads/block; chunk-split loading (8 float4/thread), then
// single-pass moment reduction + weighted Procrustes + 3x3 SVD (4 sweeps).
// (R14/R15-proven; untouched.)
// ---------------------------------------------------------------------------
__device__ __forceinline__ void warp_reduce_n(float* v, int n)
{
    for (int o = 16; o; o >>= 1)
        for (int j = 0; j < n; ++j)
            v[j] += __shfl_xor_sync(0xffffffffu, v[j], o);
}

__global__ void __launch_bounds__(256) stage2_kernel(float* __restrict__ out)
{
    const int b   = blockIdx.x;
    const int tid = threadIdx.x;
    const int cg  = tid >> 6;    // chunk group 0..3 (4 chunks each)
    const int k   = tid & 63;    // component index

    // Phase 1: each thread loads 4 chunks of both tensors (8 float4 total).
    float a[8] = {0.f, 0.f, 0.f, 0.f, 0.f, 0.f, 0.f, 0.f};
    #pragma unroll
    for (int ci = 0; ci < 4; ++ci) {
        const int c = cg * 4 + ci;
        const float4 px = __ldcg(reinterpret_cast<const float4*>(
            &g_partials[(((size_t)0 * BB + b) * CHUNKS + c) * (KK * 4) + k * 4]));
        a[0] += px.x; a[1] += px.y; a[2] += px.z; a[3] += px.w;
        const float4 py = __ldcg(reinterpret_cast<const float4*>(
            &g_partials[(((size_t)1 * BB + b) * CHUNKS + c) * (KK * 4) + k * 4]));
        a[4] += py.x; a[5] += py.y; a[6] += py.z; a[7] += py.w;
    }

    __shared__ float red[4][KK][9];   // pad 8->9 to dodge bank conflicts
    #pragma unroll
    for (int j = 0; j < 8; ++j) red[cg][k][j] = a[j];
    __syncthreads();

    __shared__ float wsum[2][16];

    // Phase 2: threads 0..63 combine the 4 chunk-groups and run the
    // 16-value moment reduction (2 warps).
    if (tid < KK) {
        const int wid  = tid >> 5;
        const int lane = tid & 31;

        float sgx = 0.f, sxx = 0.f, syx = 0.f, szx = 0.f;
        float sgy = 0.f, sxy = 0.f, syy = 0.f, szy = 0.f;
        #pragma unroll
        for (int g = 0; g < 4; ++g) {
            sgx += red[g][tid][0]; sxx += red[g][tid][1];
            syx += red[g][tid][2]; szx += red[g][tid][3];
            sgy += red[g][tid][4]; sxy += red[g][tid][5];
            syy += red[g][tid][6]; szy += red[g][tid][7];
        }

        const float EPSf = 1e-8f;
        const float pix = sgx * (1.0f / (float)NN);
        const float piy = sgy * (1.0f / (float)NN);
        const float rpx = __fdividef(1.0f, pix + EPSf);
        const float rpy = __fdividef(1.0f, piy + EPSf);
        const float mux0 = sxx * rpx, mux1 = syx * rpx, mux2 = szx * rpx;
        const float muy0 = sxy * rpy, muy1 = syy * rpy, muy2 = szy * rpy;
        const float w = pix * piy;

        float v[16] = {
            w,
            w * mux0, w * mux1, w * mux2,
            w * muy0, w * muy1, w * muy2,
            w * mux0 * muy0, w * mux0 * muy1, w * mux0 * muy2,
            w * mux1 * muy0, w * mux1 * muy1, w * mux1 * muy2,
            w * mux2 * muy0, w * mux2 * muy1, w * mux2 * muy2
        };
        warp_reduce_n(v, 16);
        if (lane == 0)
            #pragma unroll
            for (int j = 0; j < 16; ++j) wsum[wid][j] = v[j];
    }
    __syncthreads();

    if (tid == 0) {
        const float EPSf = 1e-8f;
        float s[16];
        #pragma unroll
        for (int j = 0; j < 16; ++j) s[j] = wsum[0][j] + wsum[1][j];

        const float wtot = s[0];
        const float ws = __fdividef(1.0f, wtot + EPSf);
        const float cs[3] = { s[1] * ws, s[2] * ws, s[3] * ws };   // c_s
        const float ct[3] = { s[4] * ws, s[5] * ws, s[6] * ws };   // c_t

        // H = S_xy - wtot * c_s c_t^T
        float H[3][3];
        #pragma unroll
        for (int i = 0; i < 3; ++i)
            #pragma unroll
            for (int j = 0; j < 3; ++j)
                H[i][j] = s[7 + i * 3 + j] - wtot * cs[i] * ct[j];

        // Scale H to O(1) for healthy fp32 conditioning in HtH.
        float hmax = 0.f;
        for (int i = 0; i < 3; ++i)
            for (int j = 0; j < 3; ++j) hmax = fmaxf(hmax, fabsf(H[i][j]));
        const float hscale = (hmax > 1e-30f) ? __fdividef(1.0f, hmax) : 1.0f;
        float Hs[3][3];
        for (int i = 0; i < 3; ++i)
            for (int j = 0; j < 3; ++j) Hs[i][j] = H[i][j] * hscale;

        // A = Hs^T Hs (symmetric)
        float A[3][3];
        for (int i = 0; i < 3; ++i)
            for (int j = 0; j < 3; ++j)
                A[i][j] = Hs[0][i] * Hs[0][j] + Hs[1][i] * Hs[1][j] + Hs[2][i] * Hs[2][j];

        float V[3][3] = {{1, 0, 0}, {0, 1, 0}, {0, 0, 1}};
        // Cyclic Jacobi, 4 sweeps. tau clamped so 1+tau^2 stays finite ->
        // x*rsqrtf(x) is a safe fast sqrt (R6's NaN was tau=inf).
        #pragma unroll 1
        for (int sweep = 0; sweep < 4; ++sweep) {
            const int PQ[3][2] = {{0, 1}, {0, 2}, {1, 2}};
            #pragma unroll
            for (int m = 0; m < 3; ++m) {
                const int p = PQ[m][0], q = PQ[m][1];
                const float apq = A[p][q];
                if (fabsf(apq) < 1e-35f) continue;
                const float tau_raw = __fdividef(A[q][q] - A[p][p], 2.0f * apq);
                const float atau = fminf(fabsf(tau_raw), 1e18f);   // finite tau^2
                const float x = 1.0f + atau * atau;
                const float sq = x * rsqrtf(x);                    // fast sqrt
                float tt = __fdividef(copysignf(1.0f, tau_raw), atau + sq);
                if (!isfinite(tt)) tt = 0.0f;
                const float c = rsqrtf(1.0f + tt * tt);
                const float s2 = tt * c;
                const float app = A[p][p], aqq = A[q][q];
                A[p][p] = app - tt * apq;
                A[q][q] = aqq + tt * apq;
                A[p][q] = A[q][p] = 0.0f;
                const int r = 3 - p - q;
                const float arp = A[r][p], arq = A[r][q];
                A[r][p] = A[p][r] = c * arp - s2 * arq;
                A[r][q] = A[q][r] = s2 * arp + c * arq;
                #pragma unroll
                for (int i = 0; i < 3; ++i) {
                    const float vip = V[i][p], viq = V[i][q];
                    V[i][p] = c * vip - s2 * viq;
                    V[i][q] = s2 * vip + c * viq;
                }
            }
        }

        float eig[3] = {A[0][0], A[1][1], A[2][2]};
        // Sort descending, permuting V columns
        #pragma unroll
        for (int i = 0; i < 2; ++i)
            #pragma unroll
            for (int j = i + 1; j < 3; ++j)
                if (eig[j] > eig[i]) {
                    float tmp = eig[i]; eig[i] = eig[j]; eig[j] = tmp;
                    for (int r = 0; r < 3; ++r) {
                        tmp = V[r][i]; V[r][i] = V[r][j]; V[r][j] = tmp;
                    }
                }

        // U columns: u0 = normalize(Hs v0); u1 = GS(Hs v1); u2 = u0 x u1
        float U[3][3];
        {
            float u0[3], u1[3];
            for (int i = 0; i < 3; ++i)
                u0[i] = Hs[i][0] * V[0][0] + Hs[i][1] * V[1][0] + Hs[i][2] * V[2][0];
            const float nn0 = u0[0] * u0[0] + u0[1] * u0[1] + u0[2] * u0[2];
            if (nn0 > 1e-40f) { const float r = rsqrtf(nn0); u0[0] *= r; u0[1] *= r; u0[2] *= r; }
            else { u0[0] = 1; u0[1] = 0; u0[2] = 0; }

            for (int i = 0; i < 3; ++i)
                u1[i] = Hs[i][0] * V[0][1] + Hs[i][1] * V[1][1] + Hs[i][2] * V[2][1];
            const float d01 = u1[0] * u0[0] + u1[1] * u0[1] + u1[2] * u0[2];
            u1[0] -= d01 * u0[0]; u1[1] -= d01 * u0[1]; u1[2] -= d01 * u0[2];
            const float nn1 = u1[0] * u1[0] + u1[1] * u1[1] + u1[2] * u1[2];
            if (nn1 > 1e-40f) { const float r = rsqrtf(nn1); u1[0] *= r; u1[1] *= r; u1[2] *= r; }
            else {
                // pick any unit vector orthogonal to u0
                const float ax = fabsf(u0[0]), ay = fabsf(u0[1]), az = fabsf(u0[2]);
                float e[3] = {0, 0, 0};
                if (ax <= ay && ax <= az) e[0] = 1;
                else if (ay <= az) e[1] = 1;
                else e[2] = 1;
                u1[0] = u0[1] * e[2] - u0[2] * e[1];
                u1[1] = u0[2] * e[0] - u0[0] * e[2];
                u1[2] = u0[0] * e[1] - u0[1] * e[0];
                const float rn = rsqrtf(u1[0] * u1[0] + u1[1] * u1[1] + u1[2] * u1[2]);
                u1[0] *= rn; u1[1] *= rn; u1[2] *= rn;
            }
            const float u2[3] = { u0[1] * u1[2] - u0[2] * u1[1],
                                  u0[2] * u1[0] - u0[0] * u1[2],
                                  u0[0] * u1[1] - u0[1] * u1[0] };
            for (int i = 0; i < 3; ++i) {
                U[i][0] = u0[i]; U[i][1] = u1[i]; U[i][2] = u2[i];
            }
        }

        const float detV =
            V[0][0] * (V[1][1] * V[2][2] - V[1][2] * V[2][1]) -
            V[0][1] * (V[1][0] * V[2][2] - V[1][2] * V[2][0]) +
            V[0][2] * (V[1][0] * V[2][1] - V[1][1] * V[2][0]);
        const float detU =
            U[0][0] * (U[1][1] * U[2][2] - U[1][2] * U[2][1]) -
            U[0][1] * (U[1][0] * U[2][2] - U[1][2] * U[2][0]) +
            U[0][2] * (U[1][0] * U[2][1] - U[1][1] * U[2][0]);
        const float d = detV * detU;   // det(V U^T)

        // R = V diag(1,1,d) U^T
        float R[3][3];
        for (int i = 0; i < 3; ++i)
            for (int j = 0; j < 3; ++j)
                R[i][j] = V[i][0] * U[j][0] + V[i][1] * U[j][1] + d * V[i][2] * U[j][2];

        // t = c_t - R c_s
        float tv[3];
        for (int i = 0; i < 3; ++i)
            tv[i] = ct[i] - (R[i][0] * cs[0] + R[i][1] * cs[1] + R[i][2] * cs[2]);

        // Output: R (B*9) then t (B*3)
        for (int i = 0; i < 3; ++i)
            for (int j = 0; j < 3; ++j)
                out[b * 9 + i * 3 + j] = R[i][j];
        for (int i = 0; i < 3; ++i)
            out[BB * 9 + b * 3 + i] = tv[i];
    }
}

extern "C" void kernel_launch(void* const* d_in, const int* in_sizes, int n_in,
                              void* d_out, int out_size)
{
    const float* pts_x = (const float*)d_in[0];
    const float* pts_y = (const float*)d_in[1];
    const float* gam_x = (const float*)d_in[2];
    const float* gam_y = (const float*)d_in[3];

    dim3 grid1(CHUNKS, BB, 2);
    stage1_kernel<<<grid1, 256>>>(pts_x, pts_y, gam_x, gam_y);
    stage2_kernel<<<BB, 256>>>((float*)d_out);
}